// round 1
// baseline (speedup 1.0000x reference)
#include <cuda_runtime.h>

// Problem constants
#define B_  8
#define C_  512
#define HW_ 9216
#define OC_ 1536   // 3*C

// Scratch (allocation-free rule: __device__ globals)
__device__ float g_qkv[(size_t)B_ * OC_ * HW_];   // ~453 MB: q|k|v per batch
__device__ float g_attn[(size_t)B_ * C_ * C_];    // 8 MB softmax(P)
__device__ float g_m[(size_t)B_ * C_ * C_];       // 8 MB  M = Wp @ P

// ---------------------------------------------------------------------------
// Generic batched SGEMM: C[m,n] = alpha * sum_k A[m,k] * B'[k,n] (+ bias[m])
//   TRANS_B == 0 : B' = B      (B is [K,N] row-major, ldb = row stride)
//   TRANS_B == 1 : B' = B^T    (B is [N,K] row-major, ldb = row stride)
// Tiles: 128x128x8, 256 threads, 8x8 per thread, double-buffered smem.
// All problem dims here are multiples of 128 / 8 -> no bounds checks.
// ---------------------------------------------------------------------------
template<int TRANS_B, int HAS_BIAS>
__global__ __launch_bounds__(256, 2)
void sgemm_k(const float* __restrict__ A, const float* __restrict__ Bm,
             float* __restrict__ C, const float* __restrict__ bias,
             int K, int lda, int ldb, int ldc,
             long long sA, long long sB, long long sC, float alpha)
{
    __shared__ float As[2][8][128];
    __shared__ float Bs[2][8][128];

    const int bz = blockIdx.z;
    A  += bz * sA;
    Bm += bz * sB;
    C  += bz * sC;

    const int tid = threadIdx.x;
    const int m0 = blockIdx.y * 128;
    const int n0 = blockIdx.x * 128;

    // A tile loader: 128 rows x 8 k, one float4 per thread, store transposed
    const int arow = tid >> 1;            // 0..127
    const int acol = (tid & 1) << 2;      // 0 or 4
    const float* Ap = A + (long long)(m0 + arow) * lda + acol;

    // B tile loader
    int brow, bcol;
    const float* Bp;
    if (TRANS_B) {                        // B is [N,K]; tile 128 n-rows x 8 k
        brow = tid >> 1;                  // n index 0..127
        bcol = (tid & 1) << 2;            // k 0 or 4
        Bp = Bm + (long long)(n0 + brow) * ldb + bcol;
    } else {                              // B is [K,N]; tile 8 k x 128 n
        brow = tid >> 5;                  // k 0..7
        bcol = (tid & 31) << 2;           // n 0..124
        Bp = Bm + (long long)brow * ldb + n0 + bcol;
    }

    const int ry = (tid >> 4) << 3;       // 0..120 step 8
    const int rx = (tid & 15) << 3;       // 0..120 step 8

    float acc[8][8];
    #pragma unroll
    for (int i = 0; i < 8; i++)
        #pragma unroll
        for (int j = 0; j < 8; j++) acc[i][j] = 0.f;

    // prologue: tile 0 -> buffer 0
    {
        float4 a4 = *(const float4*)Ap;
        As[0][acol + 0][arow] = a4.x;
        As[0][acol + 1][arow] = a4.y;
        As[0][acol + 2][arow] = a4.z;
        As[0][acol + 3][arow] = a4.w;
        float4 b4 = *(const float4*)Bp;
        if (TRANS_B) {
            Bs[0][bcol + 0][brow] = b4.x;
            Bs[0][bcol + 1][brow] = b4.y;
            Bs[0][bcol + 2][brow] = b4.z;
            Bs[0][bcol + 3][brow] = b4.w;
        } else {
            *(float4*)&Bs[0][brow][bcol] = b4;
        }
    }
    __syncthreads();

    const int nk = K >> 3;
    for (int kt = 0; kt < nk; kt++) {
        const int cur = kt & 1;
        float4 a4, b4;
        const bool more = (kt + 1 < nk);
        if (more) {
            a4 = *(const float4*)(Ap + (kt + 1) * 8);
            b4 = TRANS_B ? *(const float4*)(Bp + (kt + 1) * 8)
                         : *(const float4*)(Bp + (long long)(kt + 1) * 8 * ldb);
        }
        #pragma unroll
        for (int k = 0; k < 8; k++) {
            float ar[8], br[8];
            *(float4*)&ar[0] = *(const float4*)&As[cur][k][ry];
            *(float4*)&ar[4] = *(const float4*)&As[cur][k][ry + 4];
            *(float4*)&br[0] = *(const float4*)&Bs[cur][k][rx];
            *(float4*)&br[4] = *(const float4*)&Bs[cur][k][rx + 4];
            #pragma unroll
            for (int i = 0; i < 8; i++)
                #pragma unroll
                for (int j = 0; j < 8; j++)
                    acc[i][j] = fmaf(ar[i], br[j], acc[i][j]);
        }
        if (more) {
            const int nxt = cur ^ 1;
            As[nxt][acol + 0][arow] = a4.x;
            As[nxt][acol + 1][arow] = a4.y;
            As[nxt][acol + 2][arow] = a4.z;
            As[nxt][acol + 3][arow] = a4.w;
            if (TRANS_B) {
                Bs[nxt][bcol + 0][brow] = b4.x;
                Bs[nxt][bcol + 1][brow] = b4.y;
                Bs[nxt][bcol + 2][brow] = b4.z;
                Bs[nxt][bcol + 3][brow] = b4.w;
            } else {
                *(float4*)&Bs[nxt][brow][bcol] = b4;
            }
            __syncthreads();
        }
    }

    // epilogue
    #pragma unroll
    for (int i = 0; i < 8; i++) {
        const float add = HAS_BIAS ? bias[m0 + ry + i] : 0.f;
        float4 o0, o1;
        o0.x = alpha * acc[i][0] + add;
        o0.y = alpha * acc[i][1] + add;
        o0.z = alpha * acc[i][2] + add;
        o0.w = alpha * acc[i][3] + add;
        o1.x = alpha * acc[i][4] + add;
        o1.y = alpha * acc[i][5] + add;
        o1.z = alpha * acc[i][6] + add;
        o1.w = alpha * acc[i][7] + add;
        float* cp = C + (long long)(m0 + ry + i) * ldc + n0 + rx;
        *(float4*)cp       = o0;
        *(float4*)(cp + 4) = o1;
    }
}

// ---------------------------------------------------------------------------
// Row softmax over 512 columns. One block (256 threads) per row.
// ---------------------------------------------------------------------------
__global__ void softmax_k(float* __restrict__ P)
{
    __shared__ float red[8], red2[8];
    float* p = P + (long long)blockIdx.x * 512;
    const int t = threadIdx.x;

    float v0 = p[t], v1 = p[t + 256];
    float m = fmaxf(v0, v1);
    #pragma unroll
    for (int o = 16; o; o >>= 1) m = fmaxf(m, __shfl_xor_sync(0xffffffffu, m, o));
    if ((t & 31) == 0) red[t >> 5] = m;
    __syncthreads();
    m = red[0];
    #pragma unroll
    for (int i = 1; i < 8; i++) m = fmaxf(m, red[i]);

    float e0 = __expf(v0 - m), e1 = __expf(v1 - m);
    float s = e0 + e1;
    #pragma unroll
    for (int o = 16; o; o >>= 1) s += __shfl_xor_sync(0xffffffffu, s, o);
    if ((t & 31) == 0) red2[t >> 5] = s;
    __syncthreads();
    s = 0.f;
    #pragma unroll
    for (int i = 0; i < 8; i++) s += red2[i];

    const float inv = 1.0f / s;
    p[t]       = e0 * inv;
    p[t + 256] = e1 * inv;
}

// ---------------------------------------------------------------------------
extern "C" void kernel_launch(void* const* d_in, const int* in_sizes, int n_in,
                              void* d_out, int out_size)
{
    (void)in_sizes; (void)n_in; (void)out_size;
    const float* x      = (const float*)d_in[0];
    const float* w_qkv  = (const float*)d_in[1];
    const float* b_qkv  = (const float*)d_in[2];
    const float* w_proj = (const float*)d_in[3];
    const float* b_proj = (const float*)d_in[4];
    float* out = (float*)d_out;

    float *qkv, *attn, *mbuf;
    cudaGetSymbolAddress((void**)&qkv,  g_qkv);
    cudaGetSymbolAddress((void**)&attn, g_attn);
    cudaGetSymbolAddress((void**)&mbuf, g_m);

    const dim3 blk(256);
    const long long sQKV = (long long)OC_ * HW_;   // per-batch qkv block
    const long long sX   = (long long)C_ * HW_;
    const long long sP   = (long long)C_ * C_;
    const float scale = 0.044194173824159216f;     // 1/sqrt(512)

    // 1) qkv[b,o,n] = sum_c w_qkv[o,c] x[b,c,n] + b_qkv[o]
    sgemm_k<0, 1><<<dim3(HW_ / 128, OC_ / 128, B_), blk>>>(
        w_qkv, x, qkv, b_qkv,
        /*K*/C_, /*lda*/C_, /*ldb*/HW_, /*ldc*/HW_,
        0LL, sX, sQKV, 1.0f);

    // 2) logits[b,i,j] = scale * sum_n q[b,i,n] k[b,j,n]   (NT gemm)
    sgemm_k<1, 0><<<dim3(C_ / 128, C_ / 128, B_), blk>>>(
        qkv, qkv + (long long)C_ * HW_, attn, nullptr,
        /*K*/HW_, /*lda*/HW_, /*ldb*/HW_, /*ldc*/C_,
        sQKV, sQKV, sP, scale);

    // 3) softmax over j
    softmax_k<<<B_ * C_, 256>>>(attn);

    // 4) M[b] = w_proj @ P[b]   (tiny 512^3 gemm; enables fusion of proj)
    sgemm_k<0, 0><<<dim3(C_ / 128, C_ / 128, B_), blk>>>(
        w_proj, attn, mbuf, nullptr,
        /*K*/C_, /*lda*/C_, /*ldb*/C_, /*ldc*/C_,
        0LL, sP, sP, 1.0f);

    // 5) out[b,o,n] = sum_j M[b,o,j] v[b,j,n] + b_proj[o]
    sgemm_k<0, 1><<<dim3(HW_ / 128, C_ / 128, B_), blk>>>(
        mbuf, qkv + (long long)2 * C_ * HW_, out, b_proj,
        /*K*/C_, /*lda*/C_, /*ldb*/HW_, /*ldc*/HW_,
        sP, sQKV, (long long)C_ * HW_, 1.0f);
}

// round 4
// speedup vs baseline: 1.9140x; 1.9140x over previous
#include <cuda_runtime.h>
#include <cuda_bf16.h>

#define B_  8
#define C_  512
#define HW_ 9216
#define OC_ 1536

// Scratch (__device__ globals per allocation rules)
__device__ float g_qkv[(size_t)B_ * OC_ * HW_];
__device__ float g_attn[(size_t)B_ * C_ * C_];
__device__ float g_m[(size_t)B_ * C_ * C_];

// ---------------- helpers ----------------
__device__ __forceinline__ unsigned smem_u32(const void* p) {
    unsigned a;
    asm("{ .reg .u64 t; cvta.to.shared.u64 t, %1; cvt.u32.u64 %0, t; }"
        : "=r"(a) : "l"(p));
    return a;
}

__device__ __forceinline__ unsigned pack_bf(float x, float y) {
    __nv_bfloat162 t = __floats2bfloat162_rn(x, y);
    return *(unsigned*)&t;
}

// split float4 -> hi (4 bf16) and lo (4 bf16 residual), each packed in u64
__device__ __forceinline__ void split4(float4 v, unsigned long long& hi,
                                       unsigned long long& lo) {
    float hx = __bfloat162float(__float2bfloat16_rn(v.x));
    float hy = __bfloat162float(__float2bfloat16_rn(v.y));
    float hz = __bfloat162float(__float2bfloat16_rn(v.z));
    float hw = __bfloat162float(__float2bfloat16_rn(v.w));
    unsigned h0 = pack_bf(v.x, v.y), h1 = pack_bf(v.z, v.w);
    unsigned l0 = pack_bf(v.x - hx, v.y - hy), l1 = pack_bf(v.z - hz, v.w - hw);
    hi = ((unsigned long long)h1 << 32) | h0;
    lo = ((unsigned long long)l1 << 32) | l0;
}

__device__ __forceinline__ void mma16816(float* c, const unsigned* a,
                                         const unsigned* b) {
    asm volatile(
        "mma.sync.aligned.m16n8k16.row.col.f32.bf16.bf16.f32 "
        "{%0,%1,%2,%3}, {%4,%5,%6,%7}, {%8,%9}, {%0,%1,%2,%3};"
        : "+f"(c[0]), "+f"(c[1]), "+f"(c[2]), "+f"(c[3])
        : "r"(a[0]), "r"(a[1]), "r"(a[2]), "r"(a[3]), "r"(b[0]), "r"(b[1]));
}

#define LDMX4T(b0, b1, b2, b3, addr) \
    asm volatile("ldmatrix.sync.aligned.m8n8.x4.trans.shared.b16 {%0,%1,%2,%3}, [%4];" \
                 : "=r"(b0), "=r"(b1), "=r"(b2), "=r"(b3) : "r"(addr))

// ---------------------------------------------------------------------------
// mma.sync GEMM: C[m,n] = alpha * sum_k A[m,k]*B'[k,n] (+bias[m])
//   TRANS_B=0: B is [N,K] row-major (K contiguous)  -> smem [n][40] bf16
//   TRANS_B=1: B is [K,N] row-major (N contiguous)  -> smem [k][272B], ldmatrix.trans
// CTA 128x128, KBLK 32, 8 warps of 32(M)x64(N). 3-pass bf16 hi/lo split.
// ---------------------------------------------------------------------------
template<int TRANS_B, int HAS_BIAS>
__global__ __launch_bounds__(256, 2)
void gemm_mma(const float* __restrict__ A, const float* __restrict__ Bm,
              float* __restrict__ Cm, const float* __restrict__ bias,
              int K, int lda, int ldb, int ldc,
              long long sA, long long sB, long long sC, float alpha)
{
    constexpr int KBLK = 32;
    constexpr int ASZ  = 128 * 40 * 2;               // 10240 bytes per operand
    constexpr int BSZ  = TRANS_B ? (32 * 272) : ASZ; // 8704 or 10240

    static __shared__ __align__(16) unsigned char smAhi[ASZ];
    static __shared__ __align__(16) unsigned char smAlo[ASZ];
    static __shared__ __align__(16) unsigned char smBhi[BSZ];
    static __shared__ __align__(16) unsigned char smBlo[BSZ];

    const int tid = threadIdx.x;
    const int bz = blockIdx.z;
    A  += bz * sA;  Bm += bz * sB;  Cm += bz * sC;
    const int m0 = blockIdx.y * 128, n0 = blockIdx.x * 128;

    const int wid  = tid >> 5, lane = tid & 31;
    const int wm   = (wid & 3) * 32;     // warp M offset
    const int wn   = (wid >> 2) * 64;    // warp N offset
    const int gid  = lane >> 2, tig = lane & 3;

    // A loader: row = tid>>1, k-half = (tid&1)*16
    const int a_row = tid >> 1;
    const int a_kb  = (tid & 1) * 16;
    // B trans loader: k = tid>>3, n base = (tid&7)*16
    const int b_k = tid >> 3;
    const int b_n = (tid & 7) * 16;

    // ldmatrix lane offset (trans path)
    const int q = lane >> 3, rr = lane & 7;
    const unsigned bhi_a = smem_u32(smBhi);
    const unsigned blo_a = smem_u32(smBlo);
    const unsigned ldm_off = ((q & 1) * 8 + rr) * 272 + (wn + (q >> 1) * 8) * 2;

    float acc[2][8][4];
    #pragma unroll
    for (int i = 0; i < 2; i++)
        #pragma unroll
        for (int j = 0; j < 8; j++)
            #pragma unroll
            for (int t = 0; t < 4; t++) acc[i][j][t] = 0.f;

    const int nkb = K / KBLK;
    for (int kb = 0; kb < nkb; kb++) {
        // ---- stage A: rows m0..+127, k kb*32..+31
        {
            const float4* Ap = (const float4*)(A + (long long)(m0 + a_row) * lda
                                               + kb * KBLK + a_kb);
            #pragma unroll
            for (int j = 0; j < 4; j++) {
                unsigned long long hi, lo;
                split4(Ap[j], hi, lo);
                const unsigned off = (a_row * 40 + a_kb + j * 4) * 2;
                *(unsigned long long*)(smAhi + off) = hi;
                *(unsigned long long*)(smAlo + off) = lo;
            }
        }
        // ---- stage B
        if (TRANS_B) {
            const float4* Bp = (const float4*)(Bm + (long long)(kb * KBLK + b_k) * ldb
                                               + n0 + b_n);
            #pragma unroll
            for (int j = 0; j < 4; j++) {
                unsigned long long hi, lo;
                split4(Bp[j], hi, lo);
                const unsigned off = b_k * 272 + (b_n + j * 4) * 2;
                *(unsigned long long*)(smBhi + off) = hi;
                *(unsigned long long*)(smBlo + off) = lo;
            }
        } else {
            const float4* Bp = (const float4*)(Bm + (long long)(n0 + a_row) * ldb
                                               + kb * KBLK + a_kb);
            #pragma unroll
            for (int j = 0; j < 4; j++) {
                unsigned long long hi, lo;
                split4(Bp[j], hi, lo);
                const unsigned off = (a_row * 40 + a_kb + j * 4) * 2;
                *(unsigned long long*)(smBhi + off) = hi;
                *(unsigned long long*)(smBlo + off) = lo;
            }
        }
        __syncthreads();

        #pragma unroll
        for (int ks = 0; ks < 2; ks++) {
            // A fragments (hi & lo) for both 16-row m-frags
            unsigned ah[2][4], al[2][4];
            #pragma unroll
            for (int mf = 0; mf < 2; mf++) {
                const unsigned base = ((wm + mf * 16 + gid) * 40 + ks * 16 + tig * 2) * 2;
                ah[mf][0] = *(const unsigned*)(smAhi + base);
                ah[mf][1] = *(const unsigned*)(smAhi + base + 640);
                ah[mf][2] = *(const unsigned*)(smAhi + base + 16);
                ah[mf][3] = *(const unsigned*)(smAhi + base + 656);
                al[mf][0] = *(const unsigned*)(smAlo + base);
                al[mf][1] = *(const unsigned*)(smAlo + base + 640);
                al[mf][2] = *(const unsigned*)(smAlo + base + 16);
                al[mf][3] = *(const unsigned*)(smAlo + base + 656);
            }

            if (TRANS_B) {
                #pragma unroll
                for (int p = 0; p < 4; p++) {           // pairs of n-frags
                    const unsigned addr_h = bhi_a + ldm_off + ks * 16 * 272 + p * 32;
                    const unsigned addr_l = blo_a + ldm_off + ks * 16 * 272 + p * 32;
                    unsigned bh[4], bl[4];
                    LDMX4T(bh[0], bh[1], bh[2], bh[3], addr_h);
                    LDMX4T(bl[0], bl[1], bl[2], bl[3], addr_l);
                    #pragma unroll
                    for (int h = 0; h < 2; h++) {       // nf = 2p+h
                        #pragma unroll
                        for (int mf = 0; mf < 2; mf++) {
                            float* c = acc[mf][2 * p + h];
                            mma16816(c, ah[mf], bh + 2 * h);
                            mma16816(c, al[mf], bh + 2 * h);
                            mma16816(c, ah[mf], bl + 2 * h);
                        }
                    }
                }
            } else {
                #pragma unroll
                for (int nf = 0; nf < 8; nf++) {
                    const unsigned base = ((wn + nf * 8 + gid) * 40 + ks * 16 + tig * 2) * 2;
                    unsigned bh[2], bl[2];
                    bh[0] = *(const unsigned*)(smBhi + base);
                    bh[1] = *(const unsigned*)(smBhi + base + 16);
                    bl[0] = *(const unsigned*)(smBlo + base);
                    bl[1] = *(const unsigned*)(smBlo + base + 16);
                    #pragma unroll
                    for (int mf = 0; mf < 2; mf++) {
                        float* c = acc[mf][nf];
                        mma16816(c, ah[mf], bh);
                        mma16816(c, al[mf], bh);
                        mma16816(c, ah[mf], bl);
                    }
                }
            }
        }
        __syncthreads();
    }

    // ---- epilogue: direct v2 global stores (32B-sector coalesced)
    #pragma unroll
    for (int mf = 0; mf < 2; mf++) {
        const int r0 = m0 + wm + mf * 16 + gid;
        const float badd0 = HAS_BIAS ? bias[r0] : 0.f;
        const float badd1 = HAS_BIAS ? bias[r0 + 8] : 0.f;
        #pragma unroll
        for (int nf = 0; nf < 8; nf++) {
            const int col = n0 + wn + nf * 8 + tig * 2;
            float2 v0, v1;
            v0.x = alpha * acc[mf][nf][0] + badd0;
            v0.y = alpha * acc[mf][nf][1] + badd0;
            v1.x = alpha * acc[mf][nf][2] + badd1;
            v1.y = alpha * acc[mf][nf][3] + badd1;
            *(float2*)(Cm + (long long)r0 * ldc + col)       = v0;
            *(float2*)(Cm + (long long)(r0 + 8) * ldc + col) = v1;
        }
    }
}

// ---------------- softmax over 512 cols ----------------
__global__ void softmax_k(float* __restrict__ P)
{
    __shared__ float red[8], red2[8];
    float* p = P + (long long)blockIdx.x * 512;
    const int t = threadIdx.x;
    float v0 = p[t], v1 = p[t + 256];
    float m = fmaxf(v0, v1);
    #pragma unroll
    for (int o = 16; o; o >>= 1) m = fmaxf(m, __shfl_xor_sync(0xffffffffu, m, o));
    if ((t & 31) == 0) red[t >> 5] = m;
    __syncthreads();
    m = red[0];
    #pragma unroll
    for (int i = 1; i < 8; i++) m = fmaxf(m, red[i]);
    float e0 = __expf(v0 - m), e1 = __expf(v1 - m);
    float s = e0 + e1;
    #pragma unroll
    for (int o = 16; o; o >>= 1) s += __shfl_xor_sync(0xffffffffu, s, o);
    if ((t & 31) == 0) red2[t >> 5] = s;
    __syncthreads();
    s = 0.f;
    #pragma unroll
    for (int i = 0; i < 8; i++) s += red2[i];
    const float inv = 1.0f / s;
    p[t] = e0 * inv;
    p[t + 256] = e1 * inv;
}

// ---------------------------------------------------------------------------
extern "C" void kernel_launch(void* const* d_in, const int* in_sizes, int n_in,
                              void* d_out, int out_size)
{
    (void)in_sizes; (void)n_in; (void)out_size;
    const float* x      = (const float*)d_in[0];
    const float* w_qkv  = (const float*)d_in[1];
    const float* b_qkv  = (const float*)d_in[2];
    const float* w_proj = (const float*)d_in[3];
    const float* b_proj = (const float*)d_in[4];
    float* out = (float*)d_out;

    float *qkv, *attn, *mbuf;
    cudaGetSymbolAddress((void**)&qkv,  g_qkv);
    cudaGetSymbolAddress((void**)&attn, g_attn);
    cudaGetSymbolAddress((void**)&mbuf, g_m);

    const dim3 blk(256);
    const long long sQKV = (long long)OC_ * HW_;
    const long long sX   = (long long)C_ * HW_;
    const long long sP   = (long long)C_ * C_;
    const float scale = 0.044194173824159216f;   // 1/sqrt(512)

    // 1) qkv = w_qkv @ x + b_qkv          (B = x [K,N] N-contig -> trans)
    gemm_mma<1, 1><<<dim3(HW_ / 128, OC_ / 128, B_), blk>>>(
        w_qkv, x, qkv, b_qkv, C_, C_, HW_, HW_, 0LL, sX, sQKV, 1.0f);

    // 2) logits = scale * q @ k^T          (B = k [N,K] K-contig -> NT)
    gemm_mma<0, 0><<<dim3(C_ / 128, C_ / 128, B_), blk>>>(
        qkv, qkv + (long long)C_ * HW_, attn, nullptr,
        HW_, HW_, HW_, C_, sQKV, sQKV, sP, scale);

    // 3) softmax rows
    softmax_k<<<B_ * C_, 256>>>(attn);

    // 4) M = w_proj @ P                    (B = P [K,N] N-contig -> trans)
    gemm_mma<1, 0><<<dim3(C_ / 128, C_ / 128, B_), blk>>>(
        w_proj, attn, mbuf, nullptr, C_, C_, C_, C_, 0LL, sP, sP, 1.0f);

    // 5) out = M @ v + b_proj              (B = v [K,N] N-contig -> trans)
    gemm_mma<1, 1><<<dim3(HW_ / 128, C_ / 128, B_), blk>>>(
        mbuf, qkv + (long long)2 * C_ * HW_, out, b_proj,
        C_, C_, HW_, HW_, sP, sQKV, (long long)C_ * HW_, 1.0f);
}

// round 6
// speedup vs baseline: 2.2321x; 1.1662x over previous
#include <cuda_runtime.h>
#include <cuda_bf16.h>

#define B_  8
#define C_  512
#define HW_ 9216
#define OC_ 1536

typedef unsigned long long ull;

// ---- scratch (__device__ globals; allocation-free rule) ----
__device__ ull  g_xhi[(size_t)B_ * C_ * HW_ / 4];      // x split, 4 bf16 / ull
__device__ ull  g_xlo[(size_t)B_ * C_ * HW_ / 4];
__device__ ull  g_whi[(size_t)OC_ * C_ / 4];
__device__ ull  g_wlo[(size_t)OC_ * C_ / 4];
__device__ ull  g_wphi[(size_t)C_ * C_ / 4];
__device__ ull  g_wplo[(size_t)C_ * C_ / 4];
__device__ ull  g_qhi[(size_t)B_ * OC_ * HW_ / 4];     // qkv split
__device__ ull  g_qlo[(size_t)B_ * OC_ * HW_ / 4];
__device__ float g_attn[(size_t)4 * B_ * C_ * C_];     // split-K partials
__device__ ull  g_phi[(size_t)B_ * C_ * C_ / 4];       // softmax(P) split
__device__ ull  g_plo[(size_t)B_ * C_ * C_ / 4];
__device__ ull  g_mhi[(size_t)B_ * C_ * C_ / 4];       // M = Wp @ P split
__device__ ull  g_mlo[(size_t)B_ * C_ * C_ / 4];

// ---------------- helpers ----------------
__device__ __forceinline__ unsigned smem_u32(const void* p) {
    unsigned a;
    asm("{ .reg .u64 t; cvta.to.shared.u64 t, %1; cvt.u32.u64 %0, t; }"
        : "=r"(a) : "l"(p));
    return a;
}
__device__ __forceinline__ unsigned pack_bf(float x, float y) {
    __nv_bfloat162 t = __floats2bfloat162_rn(x, y);
    return *(unsigned*)&t;
}
__device__ __forceinline__ void split4(float4 v, ull& hi, ull& lo) {
    float hx = __bfloat162float(__float2bfloat16_rn(v.x));
    float hy = __bfloat162float(__float2bfloat16_rn(v.y));
    float hz = __bfloat162float(__float2bfloat16_rn(v.z));
    float hw = __bfloat162float(__float2bfloat16_rn(v.w));
    unsigned h0 = pack_bf(v.x, v.y), h1 = pack_bf(v.z, v.w);
    unsigned l0 = pack_bf(v.x - hx, v.y - hy), l1 = pack_bf(v.z - hz, v.w - hw);
    hi = ((ull)h1 << 32) | h0;
    lo = ((ull)l1 << 32) | l0;
}
__device__ __forceinline__ void mma16816(float* c, const unsigned* a,
                                         const unsigned* b) {
    asm volatile(
        "mma.sync.aligned.m16n8k16.row.col.f32.bf16.bf16.f32 "
        "{%0,%1,%2,%3}, {%4,%5,%6,%7}, {%8,%9}, {%0,%1,%2,%3};"
        : "+f"(c[0]), "+f"(c[1]), "+f"(c[2]), "+f"(c[3])
        : "r"(a[0]), "r"(a[1]), "r"(a[2]), "r"(a[3]), "r"(b[0]), "r"(b[1]));
}
#define LDMX4T(b0, b1, b2, b3, addr) \
    asm volatile("ldmatrix.sync.aligned.m8n8.x4.trans.shared.b16 {%0,%1,%2,%3}, [%4];" \
                 : "=r"(b0), "=r"(b1), "=r"(b2), "=r"(b3) : "r"(addr))
__device__ __forceinline__ void cpa16(unsigned s, const void* g) {
    asm volatile("cp.async.cg.shared.global [%0], [%1], 16;" :: "r"(s), "l"(g));
}
#define CP_COMMIT() asm volatile("cp.async.commit_group;" ::: "memory")
#define CP_WAIT(n)  asm volatile("cp.async.wait_group %0;" :: "n"(n) : "memory")

// smem stage layout (bytes)
#define STG      40960
#define OA_HI    0
#define OA_LO    10240
#define OB_HI    20480
#define OB_LO    30720
#define SMEM_DYN (2 * STG)

// ---------------------------------------------------------------------------
// bf16 hi/lo GEMM, cp.async 2-stage pipeline.
//   C[m,n] = alpha * sum_k A[m,k]*B'[k,n] (+bias[m])
//   TRANS_B=0: B arrays are [N,K] K-contig  (smem [n][40] bf16)
//   TRANS_B=1: B arrays are [K,N] N-contig  (smem [k][272B], ldmatrix.trans)
//   SPLIT_OUT=1: write bf16 hi/lo outputs; else fp32.
//   SPLITK>1:  blockIdx.z = batch*SPLITK + chunk; C indexed by z.
// CTA 128x128, KBLK 32, 8 warps of 32(M)x64(N), 3-pass hi/lo.
// ---------------------------------------------------------------------------
template<int TRANS_B, int HAS_BIAS, int SPLIT_OUT, int SPLITK>
__global__ __launch_bounds__(256, 2)
void gemm_bf(const __nv_bfloat16* __restrict__ Ahi, const __nv_bfloat16* __restrict__ Alo,
             const __nv_bfloat16* __restrict__ Bhi, const __nv_bfloat16* __restrict__ Blo,
             float* __restrict__ Cf,
             __nv_bfloat16* __restrict__ Chi, __nv_bfloat16* __restrict__ Clo,
             const float* __restrict__ bias,
             int K, int lda, int ldb, int ldc,
             long long sA, long long sB, long long sC, float alpha)
{
    extern __shared__ unsigned char sm[];
    const unsigned sbase = smem_u32(sm);
    const int tid = threadIdx.x, wid = tid >> 5, lane = tid & 31;

    const int z = blockIdx.z;
    const int bz = (SPLITK > 1) ? z / SPLITK : z;
    const int kc = (SPLITK > 1) ? z % SPLITK : 0;

    Ahi += bz * sA + (long long)kc * K;
    Alo += bz * sA + (long long)kc * K;
    if (TRANS_B) { Bhi += bz * sB + (long long)kc * K * ldb;
                   Blo += bz * sB + (long long)kc * K * ldb; }
    else         { Bhi += bz * sB + (long long)kc * K;
                   Blo += bz * sB + (long long)kc * K; }

    const int m0 = blockIdx.y * 128, n0 = blockIdx.x * 128;

    const int wm = (wid & 3) * 32, wn = (wid >> 2) * 64;
    const int gid = lane >> 2, tig = lane & 3;

    // ---- loader indices
    const int a_row = tid >> 1;
    const unsigned a_soff = a_row * 80 + (tid & 1) * 32;
    const __nv_bfloat16* Arh = Ahi + (long long)(m0 + a_row) * lda + (tid & 1) * 16;
    const __nv_bfloat16* Arl = Alo + (long long)(m0 + a_row) * lda + (tid & 1) * 16;

    const int b_k = tid >> 3;              // TRANS
    const int b_row = tid >> 1;            // NT
    unsigned b_soff;
    const __nv_bfloat16 *Brh, *Brl;
    if (TRANS_B) {
        b_soff = b_k * 272 + (tid & 7) * 32;
        Brh = Bhi + (long long)b_k * ldb + n0 + (tid & 7) * 16;
        Brl = Blo + (long long)b_k * ldb + n0 + (tid & 7) * 16;
    } else {
        b_soff = b_row * 80 + (tid & 1) * 32;
        Brh = Bhi + (long long)(n0 + b_row) * ldb + (tid & 1) * 16;
        Brl = Blo + (long long)(n0 + b_row) * ldb + (tid & 1) * 16;
    }

    // ldmatrix lane offset (TRANS path)
    const int q = lane >> 3, rr = lane & 7;
    const unsigned ldm_off = ((q & 1) * 8 + rr) * 272 + (wn + (q >> 1) * 8) * 2;

    float acc[2][8][4];
    #pragma unroll
    for (int i = 0; i < 2; i++)
        #pragma unroll
        for (int j = 0; j < 8; j++)
            #pragma unroll
            for (int t = 0; t < 4; t++) acc[i][j][t] = 0.f;

    const int nkb = K >> 5;

    // loader for k-block kb into stage st
    auto load_stage = [&](int kb, int st) {
        const unsigned sb = sbase + st * STG;
        const long long ka = (long long)kb * 32;
        cpa16(sb + OA_HI + a_soff,      Arh + ka);
        cpa16(sb + OA_HI + a_soff + 16, Arh + ka + 8);
        cpa16(sb + OA_LO + a_soff,      Arl + ka);
        cpa16(sb + OA_LO + a_soff + 16, Arl + ka + 8);
        if (TRANS_B) {
            const long long kb_off = (long long)kb * 32 * ldb;
            cpa16(sb + OB_HI + b_soff,      Brh + kb_off);
            cpa16(sb + OB_HI + b_soff + 16, Brh + kb_off + 8);
            cpa16(sb + OB_LO + b_soff,      Brl + kb_off);
            cpa16(sb + OB_LO + b_soff + 16, Brl + kb_off + 8);
        } else {
            cpa16(sb + OB_HI + b_soff,      Brh + ka);
            cpa16(sb + OB_HI + b_soff + 16, Brh + ka + 8);
            cpa16(sb + OB_LO + b_soff,      Brl + ka);
            cpa16(sb + OB_LO + b_soff + 16, Brl + ka + 8);
        }
    };

    load_stage(0, 0);
    CP_COMMIT();

    for (int kb = 0; kb < nkb; kb++) {
        const int st = kb & 1;
        if (kb + 1 < nkb) {
            load_stage(kb + 1, st ^ 1);
            CP_COMMIT();
            CP_WAIT(1);
        } else {
            CP_WAIT(0);
        }
        __syncthreads();

        const unsigned char* pAhi = sm + st * STG + OA_HI;
        const unsigned char* pAlo = sm + st * STG + OA_LO;
        const unsigned char* pBhi = sm + st * STG + OB_HI;
        const unsigned char* pBlo = sm + st * STG + OB_LO;
        const unsigned bhi_a = sbase + st * STG + OB_HI;
        const unsigned blo_a = sbase + st * STG + OB_LO;

        #pragma unroll
        for (int ks = 0; ks < 2; ks++) {
            unsigned ah[2][4], al[2][4];
            #pragma unroll
            for (int mf = 0; mf < 2; mf++) {
                const unsigned base = ((wm + mf * 16 + gid) * 40 + ks * 16 + tig * 2) * 2;
                ah[mf][0] = *(const unsigned*)(pAhi + base);
                ah[mf][1] = *(const unsigned*)(pAhi + base + 640);
                ah[mf][2] = *(const unsigned*)(pAhi + base + 16);
                ah[mf][3] = *(const unsigned*)(pAhi + base + 656);
                al[mf][0] = *(const unsigned*)(pAlo + base);
                al[mf][1] = *(const unsigned*)(pAlo + base + 640);
                al[mf][2] = *(const unsigned*)(pAlo + base + 16);
                al[mf][3] = *(const unsigned*)(pAlo + base + 656);
            }
            if (TRANS_B) {
                #pragma unroll
                for (int p = 0; p < 4; p++) {
                    unsigned bh[4], bl[4];
                    LDMX4T(bh[0], bh[1], bh[2], bh[3], bhi_a + ldm_off + ks * 16 * 272 + p * 32);
                    LDMX4T(bl[0], bl[1], bl[2], bl[3], blo_a + ldm_off + ks * 16 * 272 + p * 32);
                    #pragma unroll
                    for (int h = 0; h < 2; h++)
                        #pragma unroll
                        for (int mf = 0; mf < 2; mf++) {
                            float* c = acc[mf][2 * p + h];
                            mma16816(c, ah[mf], bh + 2 * h);
                            mma16816(c, al[mf], bh + 2 * h);
                            mma16816(c, ah[mf], bl + 2 * h);
                        }
                }
            } else {
                #pragma unroll
                for (int nf = 0; nf < 8; nf++) {
                    const unsigned base = ((wn + nf * 8 + gid) * 40 + ks * 16 + tig * 2) * 2;
                    unsigned bh[2], bl[2];
                    bh[0] = *(const unsigned*)(pBhi + base);
                    bh[1] = *(const unsigned*)(pBhi + base + 16);
                    bl[0] = *(const unsigned*)(pBlo + base);
                    bl[1] = *(const unsigned*)(pBlo + base + 16);
                    #pragma unroll
                    for (int mf = 0; mf < 2; mf++) {
                        float* c = acc[mf][nf];
                        mma16816(c, ah[mf], bh);
                        mma16816(c, al[mf], bh);
                        mma16816(c, ah[mf], bl);
                    }
                }
            }
        }
        __syncthreads();
    }

    // ---- epilogue
    #pragma unroll
    for (int mf = 0; mf < 2; mf++) {
        const int r0 = m0 + wm + mf * 16 + gid;
        const float b0 = HAS_BIAS ? bias[r0] : 0.f;
        const float b1 = HAS_BIAS ? bias[r0 + 8] : 0.f;
        #pragma unroll
        for (int nf = 0; nf < 8; nf++) {
            const int col = n0 + wn + nf * 8 + tig * 2;
            float f0 = alpha * acc[mf][nf][0] + b0;
            float f1 = alpha * acc[mf][nf][1] + b0;
            float f2 = alpha * acc[mf][nf][2] + b1;
            float f3 = alpha * acc[mf][nf][3] + b1;
            if (SPLIT_OUT) {
                __nv_bfloat16 h0 = __float2bfloat16_rn(f0), h1 = __float2bfloat16_rn(f1);
                __nv_bfloat16 h2 = __float2bfloat16_rn(f2), h3 = __float2bfloat16_rn(f3);
                unsigned hi0 = pack_bf(f0, f1);
                unsigned hi1 = pack_bf(f2, f3);
                unsigned lo0 = pack_bf(f0 - __bfloat162float(h0), f1 - __bfloat162float(h1));
                unsigned lo1 = pack_bf(f2 - __bfloat162float(h2), f3 - __bfloat162float(h3));
                long long o0 = (long long)(z * sC) + (long long)r0 * ldc + col;
                long long o1 = (long long)(z * sC) + (long long)(r0 + 8) * ldc + col;
                *(unsigned*)(Chi + o0) = hi0;
                *(unsigned*)(Clo + o0) = lo0;
                *(unsigned*)(Chi + o1) = hi1;
                *(unsigned*)(Clo + o1) = lo1;
            } else {
                float* c0 = Cf + z * sC + (long long)r0 * ldc + col;
                float* c1 = Cf + z * sC + (long long)(r0 + 8) * ldc + col;
                *(float2*)c0 = make_float2(f0, f1);
                *(float2*)c1 = make_float2(f2, f3);
            }
        }
    }
}

// ---------------- split fp32 -> bf16 hi/lo ----------------
__global__ void split_arr(const float4* __restrict__ src, ull* __restrict__ hi,
                          ull* __restrict__ lo, int n4)
{
    int i = blockIdx.x * blockDim.x + threadIdx.x;
    if (i < n4) {
        ull h, l;
        split4(src[i], h, l);
        hi[i] = h;
        lo[i] = l;
    }
}

// ---------------- fused split-K reduce + softmax + split ----------------
__global__ void softmax_red(const float* __restrict__ part,
                            __nv_bfloat16* __restrict__ phi,
                            __nv_bfloat16* __restrict__ plo)
{
    __shared__ float red[8], red2[8];
    const int row = blockIdx.x;            // b*512 + i
    const int b = row >> 9, i = row & 511;
    const int t = threadIdx.x;
    const float scale = 0.044194173824159216f;

    long long base = ((long long)b * 4) * 262144 + (long long)i * 512;
    float v0 = 0.f, v1 = 0.f;
    #pragma unroll
    for (int kc = 0; kc < 4; kc++) {
        v0 += part[base + (long long)kc * 262144 + t];
        v1 += part[base + (long long)kc * 262144 + t + 256];
    }
    v0 *= scale; v1 *= scale;

    float m = fmaxf(v0, v1);
    #pragma unroll
    for (int o = 16; o; o >>= 1) m = fmaxf(m, __shfl_xor_sync(0xffffffffu, m, o));
    if ((t & 31) == 0) red[t >> 5] = m;
    __syncthreads();
    m = red[0];
    #pragma unroll
    for (int k = 1; k < 8; k++) m = fmaxf(m, red[k]);

    float e0 = __expf(v0 - m), e1 = __expf(v1 - m);
    float s = e0 + e1;
    #pragma unroll
    for (int o = 16; o; o >>= 1) s += __shfl_xor_sync(0xffffffffu, s, o);
    if ((t & 31) == 0) red2[t >> 5] = s;
    __syncthreads();
    s = 0.f;
    #pragma unroll
    for (int k = 0; k < 8; k++) s += red2[k];
    const float inv = 1.0f / s;

    float p0 = e0 * inv, p1 = e1 * inv;
    __nv_bfloat16 h0 = __float2bfloat16_rn(p0), h1 = __float2bfloat16_rn(p1);
    long long o = (long long)row * 512;
    phi[o + t]       = h0;
    plo[o + t]       = __float2bfloat16_rn(p0 - __bfloat162float(h0));
    phi[o + t + 256] = h1;
    plo[o + t + 256] = __float2bfloat16_rn(p1 - __bfloat162float(h1));
}

// ---------------------------------------------------------------------------
extern "C" void kernel_launch(void* const* d_in, const int* in_sizes, int n_in,
                              void* d_out, int out_size)
{
    (void)in_sizes; (void)n_in; (void)out_size;
    const float* x      = (const float*)d_in[0];
    const float* w_qkv  = (const float*)d_in[1];
    const float* b_qkv  = (const float*)d_in[2];
    const float* w_proj = (const float*)d_in[3];
    const float* b_proj = (const float*)d_in[4];
    float* out = (float*)d_out;

    void *xhi, *xlo, *whi, *wlo, *wphi, *wplo, *qhi, *qlo, *attn, *phi, *plo, *mhi, *mlo;
    cudaGetSymbolAddress(&xhi, g_xhi);   cudaGetSymbolAddress(&xlo, g_xlo);
    cudaGetSymbolAddress(&whi, g_whi);   cudaGetSymbolAddress(&wlo, g_wlo);
    cudaGetSymbolAddress(&wphi, g_wphi); cudaGetSymbolAddress(&wplo, g_wplo);
    cudaGetSymbolAddress(&qhi, g_qhi);   cudaGetSymbolAddress(&qlo, g_qlo);
    cudaGetSymbolAddress(&attn, g_attn);
    cudaGetSymbolAddress(&phi, g_phi);   cudaGetSymbolAddress(&plo, g_plo);
    cudaGetSymbolAddress(&mhi, g_mhi);   cudaGetSymbolAddress(&mlo, g_mlo);

    cudaFuncSetAttribute(gemm_bf<1,1,1,1>, cudaFuncAttributeMaxDynamicSharedMemorySize, SMEM_DYN);
    cudaFuncSetAttribute(gemm_bf<0,0,0,4>, cudaFuncAttributeMaxDynamicSharedMemorySize, SMEM_DYN);
    cudaFuncSetAttribute(gemm_bf<1,0,1,1>, cudaFuncAttributeMaxDynamicSharedMemorySize, SMEM_DYN);
    cudaFuncSetAttribute(gemm_bf<1,1,0,1>, cudaFuncAttributeMaxDynamicSharedMemorySize, SMEM_DYN);

    const dim3 blk(256);
    const long long sQKV = (long long)OC_ * HW_;
    const long long sX   = (long long)C_ * HW_;
    const long long sP   = (long long)C_ * C_;

    // 0) splits
    split_arr<<<(B_ * C_ * HW_ / 4 + 255) / 256, blk>>>((const float4*)x, (ull*)xhi, (ull*)xlo, B_ * C_ * HW_ / 4);
    split_arr<<<(OC_ * C_ / 4 + 255) / 256, blk>>>((const float4*)w_qkv, (ull*)whi, (ull*)wlo, OC_ * C_ / 4);
    split_arr<<<(C_ * C_ / 4 + 255) / 256, blk>>>((const float4*)w_proj, (ull*)wphi, (ull*)wplo, C_ * C_ / 4);

    typedef __nv_bfloat16 bf;

    // 1) qkv = w_qkv @ x + b_qkv  -> split bf16
    gemm_bf<1,1,1,1><<<dim3(HW_/128, OC_/128, B_), blk, SMEM_DYN>>>(
        (const bf*)whi, (const bf*)wlo, (const bf*)xhi, (const bf*)xlo,
        nullptr, (bf*)qhi, (bf*)qlo, b_qkv,
        C_, C_, HW_, HW_, 0LL, sX, sQKV, 1.0f);

    // 2) logits partials = q @ k^T  (split-K 4)
    gemm_bf<0,0,0,4><<<dim3(C_/128, C_/128, B_*4), blk, SMEM_DYN>>>(
        (const bf*)qhi, (const bf*)qlo,
        (const bf*)qhi + (long long)C_*HW_, (const bf*)qlo + (long long)C_*HW_,
        (float*)attn, nullptr, nullptr, nullptr,
        HW_/4, HW_, HW_, C_, sQKV, sQKV, sP, 1.0f);

    // 3) reduce + scale + softmax -> P split bf16
    softmax_red<<<B_ * C_, blk>>>((const float*)attn, (bf*)phi, (bf*)plo);

    // 4) M = w_proj @ P -> split bf16
    gemm_bf<1,0,1,1><<<dim3(C_/128, C_/128, B_), blk, SMEM_DYN>>>(
        (const bf*)wphi, (const bf*)wplo, (const bf*)phi, (const bf*)plo,
        nullptr, (bf*)mhi, (bf*)mlo, nullptr,
        C_, C_, C_, C_, 0LL, sP, sP, 1.0f);

    // 5) out = M @ v + b_proj  (fp32 out)
    gemm_bf<1,1,0,1><<<dim3(HW_/128, C_/128, B_), blk, SMEM_DYN>>>(
        (const bf*)mhi, (const bf*)mlo,
        (const bf*)qhi + (long long)2*C_*HW_, (const bf*)qlo + (long long)2*C_*HW_,
        out, nullptr, nullptr, b_proj,
        C_, C_, HW_, HW_, sP, sQKV, (long long)C_*HW_, 1.0f);
}

// round 7
// speedup vs baseline: 2.9231x; 1.3096x over previous
#include <cuda_runtime.h>
#include <cuda_fp16.h>

#define B_  8
#define C_  512
#define HW_ 9216
#define OC_ 1536

typedef unsigned long long ull;

// ---- scratch (__device__ globals; allocation-free rule) ----
__device__ ull  g_xhi [(size_t)B_ * C_ * HW_ / 4];     // x fp16 (B-side, hi only)
__device__ ull  g_whi [(size_t)OC_ * C_ / 4];
__device__ ull  g_wlo [(size_t)OC_ * C_ / 4];
__device__ ull  g_wphi[(size_t)C_ * C_ / 4];
__device__ ull  g_wplo[(size_t)C_ * C_ / 4];
__device__ ull  g_qhi [(size_t)B_ * OC_ * HW_ / 4];    // qkv hi
__device__ ull  g_qlo [(size_t)B_ * OC_ * HW_ / 4];    // lo used only for q rows
__device__ float g_attn[(size_t)4 * B_ * C_ * C_];     // split-K partials
__device__ ull  g_phi [(size_t)B_ * C_ * C_ / 4];      // softmax(P) fp16 (B-side)
__device__ ull  g_mhi [(size_t)B_ * C_ * C_ / 4];      // M hi/lo (A-side)
__device__ ull  g_mlo [(size_t)B_ * C_ * C_ / 4];

// ---------------- helpers ----------------
__device__ __forceinline__ unsigned smem_u32(const void* p) {
    unsigned a;
    asm("{ .reg .u64 t; cvta.to.shared.u64 t, %1; cvt.u32.u64 %0, t; }"
        : "=r"(a) : "l"(p));
    return a;
}
__device__ __forceinline__ unsigned pack_h2(float x, float y) {
    __half2 t = __floats2half2_rn(x, y);
    return *(unsigned*)&t;
}
__device__ __forceinline__ ull pack_h4(__half a, __half b, __half c, __half d) {
    unsigned lo = (unsigned)__half_as_ushort(a) | ((unsigned)__half_as_ushort(b) << 16);
    unsigned hi = (unsigned)__half_as_ushort(c) | ((unsigned)__half_as_ushort(d) << 16);
    return ((ull)hi << 32) | lo;
}
__device__ __forceinline__ void mma_h(float* c, const unsigned* a, const unsigned* b) {
    asm volatile(
        "mma.sync.aligned.m16n8k16.row.col.f32.f16.f16.f32 "
        "{%0,%1,%2,%3}, {%4,%5,%6,%7}, {%8,%9}, {%0,%1,%2,%3};"
        : "+f"(c[0]), "+f"(c[1]), "+f"(c[2]), "+f"(c[3])
        : "r"(a[0]), "r"(a[1]), "r"(a[2]), "r"(a[3]), "r"(b[0]), "r"(b[1]));
}
#define LDMX4(r0, r1, r2, r3, addr) \
    asm volatile("ldmatrix.sync.aligned.m8n8.x4.shared.b16 {%0,%1,%2,%3}, [%4];" \
                 : "=r"(r0), "=r"(r1), "=r"(r2), "=r"(r3) : "r"(addr))
#define LDMX4T(r0, r1, r2, r3, addr) \
    asm volatile("ldmatrix.sync.aligned.m8n8.x4.trans.shared.b16 {%0,%1,%2,%3}, [%4];" \
                 : "=r"(r0), "=r"(r1), "=r"(r2), "=r"(r3) : "r"(addr))
__device__ __forceinline__ void cpa16(unsigned s, const void* g) {
    asm volatile("cp.async.cg.shared.global [%0], [%1], 16;" :: "r"(s), "l"(g));
}
#define CP_COMMIT() asm volatile("cp.async.commit_group;" ::: "memory")
#define CP_WAIT(n)  asm volatile("cp.async.wait_group %0;" :: "n"(n) : "memory")

// smem layout per stage (bytes): A rows 144B-stride, B-trans k-rows 272B-stride
#define ASTR   144
#define BTSTR  272
#define OA_HI  0
#define OA_LO  18432
#define OB     36864
#define STG    55296
#define SMEM_DYN (2 * STG)    // 110592 -> 2 CTAs/SM = 216KB

// ---------------------------------------------------------------------------
// fp16 2-pass GEMM (A = hi+lo, B = hi): C = alpha*(Ahi+Alo)@B' (+bias)
//   TRANS_B=1: B is [K,N] N-contig (ldmatrix.trans) ; TRANS_B=0: B is [N,K]
//   OUT_MODE: 0 = fp32, 2 = fp16 hi+lo, 3 = fp16 hi always / lo iff row<512
// CTA 128x128, KBLK 64, 8 warps of 32(M)x64(N).
// ---------------------------------------------------------------------------
template<int TRANS_B, int HAS_BIAS, int OUT_MODE, int SPLITK>
__global__ __launch_bounds__(256, 2)
void gemm_h(const __half* __restrict__ Ahi, const __half* __restrict__ Alo,
            const __half* __restrict__ Bhi,
            float* __restrict__ Cf,
            __half* __restrict__ Chi, __half* __restrict__ Clo,
            const float* __restrict__ bias,
            int K, int lda, int ldb, int ldc,
            long long sA, long long sB, long long sC, float alpha)
{
    extern __shared__ unsigned char sm[];
    const unsigned sbase = smem_u32(sm);
    const int tid = threadIdx.x, wid = tid >> 5, lane = tid & 31;

    const int z  = blockIdx.z;
    const int bz = (SPLITK > 1) ? z / SPLITK : z;
    const int kc = (SPLITK > 1) ? z % SPLITK : 0;

    Ahi += bz * sA + (long long)kc * K;
    Alo += bz * sA + (long long)kc * K;
    if (TRANS_B) Bhi += bz * sB + (long long)kc * K * ldb;
    else         Bhi += bz * sB + (long long)kc * K;

    const int m0 = blockIdx.y * 128, n0 = blockIdx.x * 128;
    const int wm = (wid & 3) * 32, wn = (wid >> 2) * 64;
    const int gid = lane >> 2, tig = lane & 3;

    // ---- loaders (per k-block: A 2x16KB, B 16KB)
    const int a_row = tid >> 1, a_half = tid & 1;
    const unsigned a_soff = a_row * ASTR + a_half * 64;
    const __half* Arh = Ahi + (long long)(m0 + a_row) * lda + a_half * 32;
    const __half* Arl = Alo + (long long)(m0 + a_row) * lda + a_half * 32;

    unsigned b_soff;
    const __half* Brh;
    if (TRANS_B) {
        const int b_k = tid >> 2, b_q = tid & 3;
        b_soff = b_k * BTSTR + b_q * 64;
        Brh = Bhi + (long long)b_k * ldb + n0 + b_q * 32;
    } else {
        b_soff = a_row * ASTR + a_half * 64;
        Brh = Bhi + (long long)(n0 + a_row) * ldb + a_half * 32;
    }

    // ---- fragment lane offsets
    const int g = lane >> 3, lr = lane & 7;
    const unsigned afrag = ((g & 1) * 8 + lr) * ASTR + (g >> 1) * 16;        // A non-trans
    const unsigned ldm_t = ((g & 1) * 8 + lr) * BTSTR + (wn + (g >> 1) * 8) * 2; // B trans
    const unsigned bnt   = ((g >> 1) * 8 + lr) * ASTR + (g & 1) * 16;        // B NT

    float acc[2][8][4];
    #pragma unroll
    for (int i = 0; i < 2; i++)
        #pragma unroll
        for (int j = 0; j < 8; j++)
            #pragma unroll
            for (int t = 0; t < 4; t++) acc[i][j][t] = 0.f;

    const int nkb = K >> 6;

    auto load_stage = [&](int kb, int st) {
        const unsigned sb = sbase + st * STG;
        const long long ka = (long long)kb * 64;
        #pragma unroll
        for (int j = 0; j < 4; j++) {
            cpa16(sb + OA_HI + a_soff + j * 16, Arh + ka + j * 8);
            cpa16(sb + OA_LO + a_soff + j * 16, Arl + ka + j * 8);
        }
        const long long kbo = TRANS_B ? ka * ldb : ka;
        #pragma unroll
        for (int j = 0; j < 4; j++)
            cpa16(sb + OB + b_soff + j * 16, Brh + kbo + j * 8);
    };

    load_stage(0, 0);
    CP_COMMIT();

    for (int kb = 0; kb < nkb; kb++) {
        const int st = kb & 1;
        if (kb + 1 < nkb) {
            load_stage(kb + 1, st ^ 1);
            CP_COMMIT();
            CP_WAIT(1);
        } else {
            CP_WAIT(0);
        }
        __syncthreads();

        const unsigned sA_hi = sbase + st * STG + OA_HI;
        const unsigned sA_lo = sbase + st * STG + OA_LO;
        const unsigned sB    = sbase + st * STG + OB;

        #pragma unroll
        for (int ks = 0; ks < 4; ks++) {
            unsigned ah[2][4], al[2][4];
            #pragma unroll
            for (int mf = 0; mf < 2; mf++) {
                const unsigned ab = (wm + mf * 16) * ASTR + ks * 32 + afrag;
                LDMX4(ah[mf][0], ah[mf][1], ah[mf][2], ah[mf][3], sA_hi + ab);
                LDMX4(al[mf][0], al[mf][1], al[mf][2], al[mf][3], sA_lo + ab);
            }
            if (TRANS_B) {
                #pragma unroll
                for (int p = 0; p < 4; p++) {
                    unsigned bt[4];
                    LDMX4T(bt[0], bt[1], bt[2], bt[3],
                           sB + ldm_t + ks * 16 * BTSTR + p * 32);
                    #pragma unroll
                    for (int h = 0; h < 2; h++)
                        #pragma unroll
                        for (int mf = 0; mf < 2; mf++) {
                            float* c = acc[mf][2 * p + h];
                            mma_h(c, ah[mf], bt + 2 * h);
                            mma_h(c, al[mf], bt + 2 * h);
                        }
                }
            } else {
                #pragma unroll
                for (int p = 0; p < 4; p++) {
                    unsigned bn[4];
                    LDMX4(bn[0], bn[1], bn[2], bn[3],
                          sB + (wn + p * 16) * ASTR + ks * 32 + bnt);
                    #pragma unroll
                    for (int h = 0; h < 2; h++)
                        #pragma unroll
                        for (int mf = 0; mf < 2; mf++) {
                            float* c = acc[mf][2 * p + h];
                            mma_h(c, ah[mf], bn + 2 * h);
                            mma_h(c, al[mf], bn + 2 * h);
                        }
                }
            }
        }
        __syncthreads();
    }

    // ---- epilogue
    #pragma unroll
    for (int mf = 0; mf < 2; mf++) {
        const int r0 = m0 + wm + mf * 16 + gid;
        const float b0 = HAS_BIAS ? bias[r0] : 0.f;
        const float b1 = HAS_BIAS ? bias[r0 + 8] : 0.f;
        #pragma unroll
        for (int nf = 0; nf < 8; nf++) {
            const int col = n0 + wn + nf * 8 + tig * 2;
            float f0 = alpha * acc[mf][nf][0] + b0;
            float f1 = alpha * acc[mf][nf][1] + b0;
            float f2 = alpha * acc[mf][nf][2] + b1;
            float f3 = alpha * acc[mf][nf][3] + b1;
            if (OUT_MODE == 0) {
                float* c0 = Cf + z * sC + (long long)r0 * ldc + col;
                float* c1 = Cf + z * sC + (long long)(r0 + 8) * ldc + col;
                *(float2*)c0 = make_float2(f0, f1);
                *(float2*)c1 = make_float2(f2, f3);
            } else {
                const long long o0 = (long long)z * sC + (long long)r0 * ldc + col;
                const long long o1 = (long long)z * sC + (long long)(r0 + 8) * ldc + col;
                __half h0 = __float2half_rn(f0), h1 = __float2half_rn(f1);
                __half h2 = __float2half_rn(f2), h3 = __float2half_rn(f3);
                *(unsigned*)(Chi + o0) = pack_h2(f0, f1);
                *(unsigned*)(Chi + o1) = pack_h2(f2, f3);
                const unsigned lo0 = pack_h2(f0 - __half2float(h0), f1 - __half2float(h1));
                const unsigned lo1 = pack_h2(f2 - __half2float(h2), f3 - __half2float(h3));
                if (OUT_MODE == 2) {
                    *(unsigned*)(Clo + o0) = lo0;
                    *(unsigned*)(Clo + o1) = lo1;
                } else {                       // OUT_MODE 3: lo only for q rows
                    if (r0 < C_)     *(unsigned*)(Clo + o0) = lo0;
                    if (r0 + 8 < C_) *(unsigned*)(Clo + o1) = lo1;
                }
            }
        }
    }
}

// ---------------- split fp32 -> fp16 hi(+lo) ----------------
__global__ void split_hl(const float4* __restrict__ src, ull* __restrict__ hi,
                         ull* __restrict__ lo, int n4)
{
    int i = blockIdx.x * blockDim.x + threadIdx.x;
    if (i < n4) {
        float4 v = src[i];
        __half hx = __float2half_rn(v.x), hy = __float2half_rn(v.y);
        __half hz = __float2half_rn(v.z), hw = __float2half_rn(v.w);
        hi[i] = pack_h4(hx, hy, hz, hw);
        lo[i] = pack_h4(__float2half_rn(v.x - __half2float(hx)),
                        __float2half_rn(v.y - __half2float(hy)),
                        __float2half_rn(v.z - __half2float(hz)),
                        __float2half_rn(v.w - __half2float(hw)));
    }
}
__global__ void split_hi(const float4* __restrict__ src, ull* __restrict__ hi, int n4)
{
    int i = blockIdx.x * blockDim.x + threadIdx.x;
    if (i < n4) {
        float4 v = src[i];
        hi[i] = pack_h4(__float2half_rn(v.x), __float2half_rn(v.y),
                        __float2half_rn(v.z), __float2half_rn(v.w));
    }
}

// ---------------- fused split-K reduce + softmax -> fp16 P ----------------
__global__ void softmax_red(const float* __restrict__ part, __half* __restrict__ phi)
{
    __shared__ float red[8], red2[8];
    const int row = blockIdx.x;            // b*512 + i
    const int b = row >> 9, i = row & 511;
    const int t = threadIdx.x;
    const float scale = 0.044194173824159216f;

    long long base = ((long long)b * 4) * 262144 + (long long)i * 512;
    float v0 = 0.f, v1 = 0.f;
    #pragma unroll
    for (int kc = 0; kc < 4; kc++) {
        v0 += part[base + (long long)kc * 262144 + t];
        v1 += part[base + (long long)kc * 262144 + t + 256];
    }
    v0 *= scale; v1 *= scale;

    float m = fmaxf(v0, v1);
    #pragma unroll
    for (int o = 16; o; o >>= 1) m = fmaxf(m, __shfl_xor_sync(0xffffffffu, m, o));
    if ((t & 31) == 0) red[t >> 5] = m;
    __syncthreads();
    m = red[0];
    #pragma unroll
    for (int k = 1; k < 8; k++) m = fmaxf(m, red[k]);

    float e0 = __expf(v0 - m), e1 = __expf(v1 - m);
    float s = e0 + e1;
    #pragma unroll
    for (int o = 16; o; o >>= 1) s += __shfl_xor_sync(0xffffffffu, s, o);
    if ((t & 31) == 0) red2[t >> 5] = s;
    __syncthreads();
    s = 0.f;
    #pragma unroll
    for (int k = 0; k < 8; k++) s += red2[k];
    const float inv = 1.0f / s;

    long long o = (long long)row * 512;
    phi[o + t]       = __float2half_rn(e0 * inv);
    phi[o + t + 256] = __float2half_rn(e1 * inv);
}

// ---------------------------------------------------------------------------
extern "C" void kernel_launch(void* const* d_in, const int* in_sizes, int n_in,
                              void* d_out, int out_size)
{
    (void)in_sizes; (void)n_in; (void)out_size;
    const float* x      = (const float*)d_in[0];
    const float* w_qkv  = (const float*)d_in[1];
    const float* b_qkv  = (const float*)d_in[2];
    const float* w_proj = (const float*)d_in[3];
    const float* b_proj = (const float*)d_in[4];
    float* out = (float*)d_out;

    void *xhi, *whi, *wlo, *wphi, *wplo, *qhi, *qlo, *attn, *phi, *mhi, *mlo;
    cudaGetSymbolAddress(&xhi, g_xhi);
    cudaGetSymbolAddress(&whi, g_whi);   cudaGetSymbolAddress(&wlo, g_wlo);
    cudaGetSymbolAddress(&wphi, g_wphi); cudaGetSymbolAddress(&wplo, g_wplo);
    cudaGetSymbolAddress(&qhi, g_qhi);   cudaGetSymbolAddress(&qlo, g_qlo);
    cudaGetSymbolAddress(&attn, g_attn);
    cudaGetSymbolAddress(&phi, g_phi);
    cudaGetSymbolAddress(&mhi, g_mhi);   cudaGetSymbolAddress(&mlo, g_mlo);

    cudaFuncSetAttribute(gemm_h<1,1,3,1>, cudaFuncAttributeMaxDynamicSharedMemorySize, SMEM_DYN);
    cudaFuncSetAttribute(gemm_h<0,0,0,4>, cudaFuncAttributeMaxDynamicSharedMemorySize, SMEM_DYN);
    cudaFuncSetAttribute(gemm_h<1,0,2,1>, cudaFuncAttributeMaxDynamicSharedMemorySize, SMEM_DYN);
    cudaFuncSetAttribute(gemm_h<1,1,0,1>, cudaFuncAttributeMaxDynamicSharedMemorySize, SMEM_DYN);

    const dim3 blk(256);
    const long long sQKV = (long long)OC_ * HW_;
    const long long sX   = (long long)C_ * HW_;
    const long long sP   = (long long)C_ * C_;
    typedef __half hf;

    // 0) splits
    split_hi<<<(B_ * C_ * HW_ / 4 + 255) / 256, blk>>>((const float4*)x, (ull*)xhi, B_ * C_ * HW_ / 4);
    split_hl<<<(OC_ * C_ / 4 + 255) / 256, blk>>>((const float4*)w_qkv, (ull*)whi, (ull*)wlo, OC_ * C_ / 4);
    split_hl<<<(C_ * C_ / 4 + 255) / 256, blk>>>((const float4*)w_proj, (ull*)wphi, (ull*)wplo, C_ * C_ / 4);

    // 1) qkv = w_qkv @ x + b_qkv   (hi out; lo for q rows)
    gemm_h<1,1,3,1><<<dim3(HW_/128, OC_/128, B_), blk, SMEM_DYN>>>(
        (const hf*)whi, (const hf*)wlo, (const hf*)xhi,
        nullptr, (hf*)qhi, (hf*)qlo, b_qkv,
        C_, C_, HW_, HW_, 0LL, sX, sQKV, 1.0f);

    // 2) logits partials = q @ k^T  (split-K 4, fp32 partials)
    gemm_h<0,0,0,4><<<dim3(C_/128, C_/128, B_*4), blk, SMEM_DYN>>>(
        (const hf*)qhi, (const hf*)qlo, (const hf*)qhi + (long long)C_*HW_,
        (float*)attn, nullptr, nullptr, nullptr,
        HW_/4, HW_, HW_, C_, sQKV, sQKV, sP, 1.0f);

    // 3) reduce + scale + softmax -> P fp16
    softmax_red<<<B_ * C_, blk>>>((const float*)attn, (hf*)phi);

    // 4) M = w_proj @ P   (hi+lo out)
    gemm_h<1,0,2,1><<<dim3(C_/128, C_/128, B_), blk, SMEM_DYN>>>(
        (const hf*)wphi, (const hf*)wplo, (const hf*)phi,
        nullptr, (hf*)mhi, (hf*)mlo, nullptr,
        C_, C_, C_, C_, 0LL, sP, sP, 1.0f);

    // 5) out = M @ v + b_proj  (fp32 out)
    gemm_h<1,1,0,1><<<dim3(HW_/128, C_/128, B_), blk, SMEM_DYN>>>(
        (const hf*)mhi, (const hf*)mlo, (const hf*)qhi + (long long)2*C_*HW_,
        out, nullptr, nullptr, b_proj,
        C_, C_, HW_, HW_, sP, sQKV, (long long)C_*HW_, 1.0f);
}

// round 13
// speedup vs baseline: 3.9482x; 1.3507x over previous
#include <cuda_runtime.h>
#include <cuda_fp16.h>

#define B_  8
#define C_  512
#define HW_ 9216
#define OC_ 1536

typedef unsigned long long ull;

// ---- scratch (__device__ globals; allocation-free rule) ----
__device__ ull  g_xhi [(size_t)B_ * C_ * HW_ / 4];     // x fp16 (B-side)
__device__ ull  g_whi [(size_t)OC_ * C_ / 4];
__device__ ull  g_wlo [(size_t)OC_ * C_ / 4];
__device__ ull  g_wphi[(size_t)C_ * C_ / 4];
__device__ ull  g_wplo[(size_t)C_ * C_ / 4];
__device__ ull  g_qhi [(size_t)B_ * OC_ * HW_ / 4];    // qkv hi
__device__ ull  g_qlo [(size_t)B_ * OC_ * HW_ / 4];    // lo used for q rows only
__device__ float g_attn[(size_t)4 * B_ * C_ * C_];     // split-K partials
__device__ ull  g_phi [(size_t)B_ * C_ * C_ / 4];      // softmax(P) fp16
__device__ ull  g_mhi [(size_t)B_ * C_ * C_ / 4];      // M hi/lo
__device__ ull  g_mlo [(size_t)B_ * C_ * C_ / 4];

// ---------------- helpers ----------------
__device__ __forceinline__ unsigned smem_u32(const void* p) {
    unsigned a;
    asm("{ .reg .u64 t; cvta.to.shared.u64 t, %1; cvt.u32.u64 %0, t; }"
        : "=r"(a) : "l"(p));
    return a;
}
__device__ __forceinline__ unsigned pack_h2(float x, float y) {
    __half2 t = __floats2half2_rn(x, y);
    return *(unsigned*)&t;
}
__device__ __forceinline__ ull pack_h4(__half a, __half b, __half c, __half d) {
    unsigned lo = (unsigned)__half_as_ushort(a) | ((unsigned)__half_as_ushort(b) << 16);
    unsigned hi = (unsigned)__half_as_ushort(c) | ((unsigned)__half_as_ushort(d) << 16);
    return ((ull)hi << 32) | lo;
}
__device__ __forceinline__ void mma_h(float* c, const unsigned* a, const unsigned* b) {
    asm volatile(
        "mma.sync.aligned.m16n8k16.row.col.f32.f16.f16.f32 "
        "{%0,%1,%2,%3}, {%4,%5,%6,%7}, {%8,%9}, {%0,%1,%2,%3};"
        : "+f"(c[0]), "+f"(c[1]), "+f"(c[2]), "+f"(c[3])
        : "r"(a[0]), "r"(a[1]), "r"(a[2]), "r"(a[3]), "r"(b[0]), "r"(b[1]));
}
#define LDMX4(r0, r1, r2, r3, addr) \
    asm volatile("ldmatrix.sync.aligned.m8n8.x4.shared.b16 {%0,%1,%2,%3}, [%4];" \
                 : "=r"(r0), "=r"(r1), "=r"(r2), "=r"(r3) : "r"(addr))
#define LDMX4T(r0, r1, r2, r3, addr) \
    asm volatile("ldmatrix.sync.aligned.m8n8.x4.trans.shared.b16 {%0,%1,%2,%3}, [%4];" \
                 : "=r"(r0), "=r"(r1), "=r"(r2), "=r"(r3) : "r"(addr))
__device__ __forceinline__ void cpa16(unsigned s, const void* g) {
    asm volatile("cp.async.cg.shared.global [%0], [%1], 16;" :: "r"(s), "l"(g));
}
#define CP_COMMIT() asm volatile("cp.async.commit_group;" ::: "memory")
#define CP_WAIT(n)  asm volatile("cp.async.wait_group %0;" :: "n"(n) : "memory")

// smem per stage: A rows 80B-stride (32 halves + 16B pad, 16B-aligned for
// ldmatrix; 80B stride => 8 consecutive rows hit 8 distinct 16B chunks mod
// 128B => conflict-free). B-trans k-rows 272B-stride.
#define ASTR   80
#define BTSTR  272
#define OA_HI  0
#define OA_LO  10240
#define OB     20480
#define STG    30720
#define SMEM_DYN (3 * STG)    // 92160 B -> 2 CTAs/SM (184 KB)

// ---------------------------------------------------------------------------
// fp16 GEMM: C = alpha * (Ahi [+ Alo]) @ B' (+bias)
//   TRANS_B=1: B is [K,N] N-contig (ldmatrix.trans) ; 0: B is [N,K] K-contig
//   OUT_MODE: 0 = fp32, 1 = fp16 hi only, 2 = fp16 hi+lo
//   PASSES: 1 or 2 (Alo pass)
// CTA 128x128, KBLK 32, 3-stage cp.async pipeline, 8 warps of 32(M)x64(N).
// ---------------------------------------------------------------------------
template<int TRANS_B, int HAS_BIAS, int OUT_MODE, int SPLITK, int PASSES>
__global__ __launch_bounds__(256, 2)
void gemm_h(const __half* __restrict__ Ahi, const __half* __restrict__ Alo,
            const __half* __restrict__ Bhi,
            float* __restrict__ Cf,
            __half* __restrict__ Chi, __half* __restrict__ Clo,
            const float* __restrict__ bias,
            int K, int lda, int ldb, int ldc,
            long long sA, long long sB, long long sC, float alpha)
{
    extern __shared__ unsigned char sm[];
    const unsigned sbase = smem_u32(sm);
    const int tid = threadIdx.x, wid = tid >> 5, lane = tid & 31;

    const int z  = blockIdx.z;
    const int bz = (SPLITK > 1) ? z / SPLITK : z;
    const int kc = (SPLITK > 1) ? z % SPLITK : 0;

    Ahi += bz * sA + (long long)kc * K;
    Alo += bz * sA + (long long)kc * K;
    if (TRANS_B) Bhi += bz * sB + (long long)kc * K * ldb;
    else         Bhi += bz * sB + (long long)kc * K;

    const int m0 = blockIdx.y * 128, n0 = blockIdx.x * 128;
    const int wm = (wid & 3) * 32, wn = (wid >> 2) * 64;
    const int gid = lane >> 2, tig = lane & 3;

    // ---- loader indices (per kblock: A 8KB (+8KB lo), B 8KB)
    const int a_row = tid >> 1, a_half = tid & 1;
    const unsigned a_soff = a_row * ASTR + a_half * 32;
    const __half* Arh = Ahi + (long long)(m0 + a_row) * lda + a_half * 16;
    const __half* Arl = Alo + (long long)(m0 + a_row) * lda + a_half * 16;

    unsigned b_soff;
    const __half* Brh;
    if (TRANS_B) {
        const int b_k = tid >> 3, b_q = tid & 7;
        b_soff = b_k * BTSTR + b_q * 32;
        Brh = Bhi + (long long)b_k * ldb + n0 + b_q * 16;
    } else {
        b_soff = a_row * ASTR + a_half * 32;
        Brh = Bhi + (long long)(n0 + a_row) * ldb + a_half * 16;
    }

    // ---- fragment lane offsets (all 16B-aligned: ASTR,BTSTR mult of 16)
    const int g = lane >> 3, lr = lane & 7;
    const unsigned afrag = ((g & 1) * 8 + lr) * ASTR + (g >> 1) * 16;            // A & B-NT
    const unsigned ldm_t = ((g & 1) * 8 + lr) * BTSTR + (wn + (g >> 1) * 8) * 2; // B trans
    const unsigned bnt   = ((g >> 1) * 8 + lr) * ASTR + (g & 1) * 16;            // B NT

    float acc[2][8][4];
    #pragma unroll
    for (int i = 0; i < 2; i++)
        #pragma unroll
        for (int j = 0; j < 8; j++)
            #pragma unroll
            for (int t = 0; t < 4; t++) acc[i][j][t] = 0.f;

    const int nkb = K >> 5;

    auto load_stage = [&](int kb, int st) {
        const unsigned sb = sbase + st * STG;
        const long long ka = (long long)kb * 32;
        #pragma unroll
        for (int j = 0; j < 2; j++) {
            cpa16(sb + OA_HI + a_soff + j * 16, Arh + ka + j * 8);
            if (PASSES == 2)
                cpa16(sb + OA_LO + a_soff + j * 16, Arl + ka + j * 8);
        }
        const long long kbo = TRANS_B ? ka * ldb : ka;
        #pragma unroll
        for (int j = 0; j < 2; j++)
            cpa16(sb + OB + b_soff + j * 16, Brh + kbo + j * 8);
    };

    // prologue: 2 stages in flight
    load_stage(0, 0); CP_COMMIT();
    if (nkb > 1) { load_stage(1, 1); } CP_COMMIT();

    int st = 0, ld = 2;                    // compute stage, next load stage
    for (int kb = 0; kb < nkb; kb++) {
        CP_WAIT(1);
        __syncthreads();

        if (kb + 2 < nkb) { load_stage(kb + 2, ld); }
        CP_COMMIT();
        if (++ld == 3) ld = 0;

        const unsigned sA_hi = sbase + st * STG + OA_HI;
        const unsigned sA_lo = sbase + st * STG + OA_LO;
        const unsigned sB    = sbase + st * STG + OB;
        if (++st == 3) st = 0;

        #pragma unroll
        for (int ks = 0; ks < 2; ks++) {
            unsigned ah[2][4], al[2][4];
            #pragma unroll
            for (int mf = 0; mf < 2; mf++) {
                const unsigned ab = (wm + mf * 16) * ASTR + ks * 16 * 2 + afrag;
                LDMX4(ah[mf][0], ah[mf][1], ah[mf][2], ah[mf][3], sA_hi + ab);
                if (PASSES == 2)
                    LDMX4(al[mf][0], al[mf][1], al[mf][2], al[mf][3], sA_lo + ab);
            }
            if (TRANS_B) {
                #pragma unroll
                for (int p = 0; p < 4; p++) {
                    unsigned bt[4];
                    LDMX4T(bt[0], bt[1], bt[2], bt[3],
                           sB + ldm_t + ks * 16 * BTSTR + p * 32);
                    #pragma unroll
                    for (int h = 0; h < 2; h++)
                        #pragma unroll
                        for (int mf = 0; mf < 2; mf++) {
                            float* c = acc[mf][2 * p + h];
                            mma_h(c, ah[mf], bt + 2 * h);
                            if (PASSES == 2) mma_h(c, al[mf], bt + 2 * h);
                        }
                }
            } else {
                #pragma unroll
                for (int p = 0; p < 4; p++) {
                    unsigned bn[4];
                    LDMX4(bn[0], bn[1], bn[2], bn[3],
                          sB + (wn + p * 16) * ASTR + ks * 16 * 2 + bnt);
                    #pragma unroll
                    for (int h = 0; h < 2; h++)
                        #pragma unroll
                        for (int mf = 0; mf < 2; mf++) {
                            float* c = acc[mf][2 * p + h];
                            mma_h(c, ah[mf], bn + 2 * h);
                            if (PASSES == 2) mma_h(c, al[mf], bn + 2 * h);
                        }
                }
            }
        }
        __syncthreads();
    }

    // ---- epilogue
    #pragma unroll
    for (int mf = 0; mf < 2; mf++) {
        const int r0 = m0 + wm + mf * 16 + gid;
        const float b0 = HAS_BIAS ? bias[r0] : 0.f;
        const float b1 = HAS_BIAS ? bias[r0 + 8] : 0.f;
        #pragma unroll
        for (int nf = 0; nf < 8; nf++) {
            const int col = n0 + wn + nf * 8 + tig * 2;
            float f0 = alpha * acc[mf][nf][0] + b0;
            float f1 = alpha * acc[mf][nf][1] + b0;
            float f2 = alpha * acc[mf][nf][2] + b1;
            float f3 = alpha * acc[mf][nf][3] + b1;
            if (OUT_MODE == 0) {
                float* c0 = Cf + z * sC + (long long)r0 * ldc + col;
                float* c1 = Cf + z * sC + (long long)(r0 + 8) * ldc + col;
                *(float2*)c0 = make_float2(f0, f1);
                *(float2*)c1 = make_float2(f2, f3);
            } else {
                const long long o0 = (long long)z * sC + (long long)r0 * ldc + col;
                const long long o1 = (long long)z * sC + (long long)(r0 + 8) * ldc + col;
                *(unsigned*)(Chi + o0) = pack_h2(f0, f1);
                *(unsigned*)(Chi + o1) = pack_h2(f2, f3);
                if (OUT_MODE == 2) {
                    __half h0 = __float2half_rn(f0), h1 = __float2half_rn(f1);
                    __half h2 = __float2half_rn(f2), h3 = __float2half_rn(f3);
                    *(unsigned*)(Clo + o0) =
                        pack_h2(f0 - __half2float(h0), f1 - __half2float(h1));
                    *(unsigned*)(Clo + o1) =
                        pack_h2(f2 - __half2float(h2), f3 - __half2float(h3));
                }
            }
        }
    }
}

// ---------------- split fp32 -> fp16 hi(+lo) ----------------
__global__ void split_hl(const float4* __restrict__ src, ull* __restrict__ hi,
                         ull* __restrict__ lo, int n4)
{
    int i = blockIdx.x * blockDim.x + threadIdx.x;
    if (i < n4) {
        float4 v = src[i];
        __half hx = __float2half_rn(v.x), hy = __float2half_rn(v.y);
        __half hz = __float2half_rn(v.z), hw = __float2half_rn(v.w);
        hi[i] = pack_h4(hx, hy, hz, hw);
        lo[i] = pack_h4(__float2half_rn(v.x - __half2float(hx)),
                        __float2half_rn(v.y - __half2float(hy)),
                        __float2half_rn(v.z - __half2float(hz)),
                        __float2half_rn(v.w - __half2float(hw)));
    }
}
__global__ void split_hi(const float4* __restrict__ src, ull* __restrict__ hi, int n4)
{
    int i = blockIdx.x * blockDim.x + threadIdx.x;
    if (i < n4) {
        float4 v = src[i];
        hi[i] = pack_h4(__float2half_rn(v.x), __float2half_rn(v.y),
                        __float2half_rn(v.z), __float2half_rn(v.w));
    }
}

// ---------------- fused split-K reduce + softmax -> fp16 P ----------------
__global__ void softmax_red(const float* __restrict__ part, __half* __restrict__ phi)
{
    __shared__ float red[8], red2[8];
    const int row = blockIdx.x;
    const int b = row >> 9, i = row & 511;
    const int t = threadIdx.x;
    const float scale = 0.044194173824159216f;

    long long base = ((long long)b * 4) * 262144 + (long long)i * 512;
    float v0 = 0.f, v1 = 0.f;
    #pragma unroll
    for (int kcc = 0; kcc < 4; kcc++) {
        v0 += part[base + (long long)kcc * 262144 + t];
        v1 += part[base + (long long)kcc * 262144 + t + 256];
    }
    v0 *= scale; v1 *= scale;

    float m = fmaxf(v0, v1);
    #pragma unroll
    for (int o = 16; o; o >>= 1) m = fmaxf(m, __shfl_xor_sync(0xffffffffu, m, o));
    if ((t & 31) == 0) red[t >> 5] = m;
    __syncthreads();
    m = red[0];
    #pragma unroll
    for (int k = 1; k < 8; k++) m = fmaxf(m, red[k]);

    float e0 = __expf(v0 - m), e1 = __expf(v1 - m);
    float s = e0 + e1;
    #pragma unroll
    for (int o = 16; o; o >>= 1) s += __shfl_xor_sync(0xffffffffu, s, o);
    if ((t & 31) == 0) red2[t >> 5] = s;
    __syncthreads();
    s = 0.f;
    #pragma unroll
    for (int k = 0; k < 8; k++) s += red2[k];
    const float inv = 1.0f / s;

    long long o = (long long)row * 512;
    phi[o + t]       = __float2half_rn(e0 * inv);
    phi[o + t + 256] = __float2half_rn(e1 * inv);
}

// ---------------------------------------------------------------------------
extern "C" void kernel_launch(void* const* d_in, const int* in_sizes, int n_in,
                              void* d_out, int out_size)
{
    (void)in_sizes; (void)n_in; (void)out_size;
    const float* x      = (const float*)d_in[0];
    const float* w_qkv  = (const float*)d_in[1];
    const float* b_qkv  = (const float*)d_in[2];
    const float* w_proj = (const float*)d_in[3];
    const float* b_proj = (const float*)d_in[4];
    float* out = (float*)d_out;

    void *xhi, *whi, *wlo, *wphi, *wplo, *qhi, *qlo, *attn, *phi, *mhi, *mlo;
    cudaGetSymbolAddress(&xhi, g_xhi);
    cudaGetSymbolAddress(&whi, g_whi);   cudaGetSymbolAddress(&wlo, g_wlo);
    cudaGetSymbolAddress(&wphi, g_wphi); cudaGetSymbolAddress(&wplo, g_wplo);
    cudaGetSymbolAddress(&qhi, g_qhi);   cudaGetSymbolAddress(&qlo, g_qlo);
    cudaGetSymbolAddress(&attn, g_attn);
    cudaGetSymbolAddress(&phi, g_phi);
    cudaGetSymbolAddress(&mhi, g_mhi);   cudaGetSymbolAddress(&mlo, g_mlo);

    cudaFuncSetAttribute(gemm_h<1,1,2,1,2>, cudaFuncAttributeMaxDynamicSharedMemorySize, SMEM_DYN);
    cudaFuncSetAttribute(gemm_h<1,1,1,1,1>, cudaFuncAttributeMaxDynamicSharedMemorySize, SMEM_DYN);
    cudaFuncSetAttribute(gemm_h<0,0,0,4,2>, cudaFuncAttributeMaxDynamicSharedMemorySize, SMEM_DYN);
    cudaFuncSetAttribute(gemm_h<1,0,2,1,2>, cudaFuncAttributeMaxDynamicSharedMemorySize, SMEM_DYN);
    cudaFuncSetAttribute(gemm_h<1,1,0,1,2>, cudaFuncAttributeMaxDynamicSharedMemorySize, SMEM_DYN);

    const dim3 blk(256);
    const long long sQKV = (long long)OC_ * HW_;
    const long long sX   = (long long)C_ * HW_;
    const long long sP   = (long long)C_ * C_;
    typedef __half hf;

    // 0) splits
    split_hi<<<(B_ * C_ * HW_ / 4 + 255) / 256, blk>>>((const float4*)x, (ull*)xhi, B_ * C_ * HW_ / 4);
    split_hl<<<(OC_ * C_ / 4 + 255) / 256, blk>>>((const float4*)w_qkv, (ull*)whi, (ull*)wlo, OC_ * C_ / 4);
    split_hl<<<(C_ * C_ / 4 + 255) / 256, blk>>>((const float4*)w_proj, (ull*)wphi, (ull*)wplo, C_ * C_ / 4);

    // 1a) q rows: 2-pass, hi+lo out
    gemm_h<1,1,2,1,2><<<dim3(HW_/128, C_/128, B_), blk, SMEM_DYN>>>(
        (const hf*)whi, (const hf*)wlo, (const hf*)xhi,
        nullptr, (hf*)qhi, (hf*)qlo, b_qkv,
        C_, C_, HW_, HW_, 0LL, sX, sQKV, 1.0f);

    // 1b) k,v rows: 1-pass, hi out (rows 512..1535 of w_qkv)
    gemm_h<1,1,1,1,1><<<dim3(HW_/128, (OC_-C_)/128, B_), blk, SMEM_DYN>>>(
        (const hf*)whi + (long long)C_*C_, nullptr, (const hf*)xhi,
        nullptr, (hf*)qhi + (long long)C_*HW_, nullptr, b_qkv + C_,
        C_, C_, HW_, HW_, 0LL, sX, sQKV, 1.0f);

    // 2) logits partials = q @ k^T (split-K 4, 2-pass, fp32 partials)
    gemm_h<0,0,0,4,2><<<dim3(C_/128, C_/128, B_*4), blk, SMEM_DYN>>>(
        (const hf*)qhi, (const hf*)qlo, (const hf*)qhi + (long long)C_*HW_,
        (float*)attn, nullptr, nullptr, nullptr,
        HW_/4, HW_, HW_, C_, sQKV, sQKV, sP, 1.0f);

    // 3) reduce + scale + softmax -> P fp16
    softmax_red<<<B_ * C_, blk>>>((const float*)attn, (hf*)phi);

    // 4) M = w_proj @ P (2-pass, hi+lo out)
    gemm_h<1,0,2,1,2><<<dim3(C_/128, C_/128, B_), blk, SMEM_DYN>>>(
        (const hf*)wphi, (const hf*)wplo, (const hf*)phi,
        nullptr, (hf*)mhi, (hf*)mlo, nullptr,
        C_, C_, C_, C_, 0LL, sP, sP, 1.0f);

    // 5) out = M @ v + b_proj (2-pass, fp32 out)
    gemm_h<1,1,0,1,2><<<dim3(HW_/128, C_/128, B_), blk, SMEM_DYN>>>(
        (const hf*)mhi, (const hf*)mlo, (const hf*)qhi + (long long)2*C_*HW_,
        out, nullptr, nullptr, b_proj,
        C_, C_, HW_, HW_, sP, sQKV, (long long)C_*HW_, 1.0f);
}